// round 16
// baseline (speedup 1.0000x reference)
#include <cuda_runtime.h>
#include <cuda_fp16.h>
#include <math.h>

#define HWSZ 16384
#define CHN  256
#define KQ   1024
#define NQ   2048
#define HSLOTS 256
#define TSB 12   // transposed activation stride (8 q + 4 pad), 48B rows

// ---------------- device scratch (static, allocation-free) ----------------
__device__ unsigned short g_val[(size_t)2 * 4 * HWSZ * CHN];  // fp16 [b*4+f][y][x][c], +time_pos
__device__ unsigned g_keys[2 * HWSZ];
__device__ int      g_ind[NQ];
__device__ float    g_q[NQ * CHN];
__device__ float    g_qpos[NQ * CHN];
__device__ float    g_so[NQ * CHN];
__device__ float    g_aw[NQ * 128];

// ---------------- f32x2 packed helpers ----------------
typedef unsigned long long ull;
__device__ __forceinline__ ull pk2(float x, float y) {
    ull r;
    asm("mov.b64 %0, {%1, %2};" : "=l"(r) : "f"(x), "f"(y));
    return r;
}
__device__ __forceinline__ void upk2(ull v, float& x, float& y) {
    asm("mov.b64 {%0, %1}, %2;" : "=f"(x), "=f"(y) : "l"(v));
}
__device__ __forceinline__ ull fma2(ull a, ull b, ull c) {
    ull d;
    asm("fma.rn.f32x2 %0, %1, %2, %3;" : "=l"(d) : "l"(a), "l"(b), "l"(c));
    return d;
}
__device__ __forceinline__ unsigned h2pack(float a, float b) {
    __half2 h = __floats2half2_rn(a, b);
    return *(unsigned*)&h;
}
__device__ __forceinline__ float h2f(unsigned short r) {
    __half h = *(__half*)&r;
    return __half2float(h);
}

__device__ __forceinline__ float gelu_tanh(float v) {
    float c = 0.7978845608028654f * (v + 0.044715f * v * v * v);
    return 0.5f * v * (1.0f + tanhf(c));
}

// ---------------- K1: transpose x -> g_val fp16 (+time_pos) ----------------
__global__ __launch_bounds__(256) void k_transpose(const float* __restrict__ x,
                                                   const float* __restrict__ tp) {
    __shared__ float tile[32][33];
    int xt = blockIdx.x * 32;
    int ct = blockIdx.y * 32;
    int z  = blockIdx.z;
    int y  = z & 127;
    int bf = z >> 7;
    int f  = bf & 3;
    int tid = threadIdx.x;

    {
        int c = tid >> 3, xq = tid & 7;
        const float4 v = *(const float4*)&x[((size_t)(bf * CHN + ct + c) * 128 + y) * 128 + xt + xq * 4];
        tile[c][xq * 4 + 0] = v.x;
        tile[c][xq * 4 + 1] = v.y;
        tile[c][xq * 4 + 2] = v.z;
        tile[c][xq * 4 + 3] = v.w;
    }
    __syncthreads();
    {
        int row = tid >> 3, quad = tid & 7;
        const float4 tq = *(const float4*)&tp[f * CHN + ct + quad * 4];
        float o0 = tile[quad * 4 + 0][row] + tq.x;
        float o1 = tile[quad * 4 + 1][row] + tq.y;
        float o2 = tile[quad * 4 + 2][row] + tq.z;
        float o3 = tile[quad * 4 + 3][row] + tq.w;
        uint2 packed = make_uint2(h2pack(o0, o1), h2pack(o2, o3));
        *(uint2*)&g_val[((size_t)(bf * 128 + y) * 128 + xt + row) * CHN + ct + quad * 4] = packed;
    }
}

// ---------------- K2a: channel-max score -> orderable keys ----------------
__global__ __launch_bounds__(1024) void k_score(const float* __restrict__ hm) {
    int i = blockIdx.x * 1024 + threadIdx.x;
    int b = i >> 14, cell = i & (HWSZ - 1);
    const float* hb = hm + (size_t)b * 10 * HWSZ + cell;
    float m = hb[0];
    #pragma unroll
    for (int c = 1; c < 10; c++) m = fmaxf(m, hb[c * HWSZ]);
    unsigned u = __float_as_uint(m);
    u = (u & 0x80000000u) ? ~u : (u | 0x80000000u);
    g_keys[i] = u;
}

// ---------------- K2b: radix top-1024 per batch ----------------
__global__ __launch_bounds__(1024) void k_topk() {
    int b = blockIdx.x, t = threadIdx.x;
    __shared__ unsigned hist[256];
    __shared__ unsigned suf[256];
    __shared__ unsigned sh[4];

    unsigned prefix = 0, r = KQ;
    for (int byte = 3; byte >= 0; byte--) {
        if (t < 256) hist[t] = 0;
        __syncthreads();
        int sh8 = byte * 8;
        unsigned pm = (byte == 3) ? 0u : (0xFFFFFFFFu << (8 * (byte + 1)));
        for (int i = t; i < HWSZ; i += 1024) {
            unsigned k = g_keys[b * HWSZ + i];
            if ((k & pm) == (prefix & pm)) atomicAdd(&hist[(k >> sh8) & 255u], 1u);
        }
        __syncthreads();
        if (t < 256) suf[t] = hist[t];
        __syncthreads();
        #pragma unroll
        for (int off = 1; off < 256; off <<= 1) {
            unsigned add = 0;
            if (t < 256 && t + off < 256) add = suf[t + off];
            __syncthreads();
            if (t < 256) suf[t] += add;
            __syncthreads();
        }
        if (t < 256) {
            unsigned nxt = (t == 255) ? 0u : suf[t + 1];
            if (suf[t] >= r && nxt < r) { sh[0] = (unsigned)t; sh[1] = r - nxt; }
        }
        __syncthreads();
        prefix |= sh[0] << sh8;
        r = sh[1];
        __syncthreads();
    }
    unsigned T = prefix;
    if (t == 0) { sh[2] = 0; sh[3] = 0; }
    __syncthreads();
    for (int i = t; i < HWSZ; i += 1024)
        if (g_keys[b * HWSZ + i] > T) atomicAdd(&sh[2], 1u);
    __syncthreads();
    unsigned cgt = sh[2];
    unsigned neq = KQ - cgt;
    __syncthreads();
    if (t == 0) sh[2] = 0;
    __syncthreads();
    for (int i = t; i < HWSZ; i += 1024) {
        unsigned k = g_keys[b * HWSZ + i];
        if (k > T) {
            unsigned s = atomicAdd(&sh[2], 1u);
            g_ind[b * KQ + s] = i;
        } else if (k == T) {
            unsigned e = atomicAdd(&sh[3], 1u);
            if (e < neq) g_ind[b * KQ + cgt + e] = i;
        }
    }
}

// ---------------- K3: query-init MLP + positional embed gather (2 q/block) ----------------
__global__ __launch_bounds__(256) void k_qinit(
    const float* __restrict__ preds,
    const float* __restrict__ W1, const float* __restrict__ b1,
    const float* __restrict__ W2, const float* __restrict__ b2,
    const float* __restrict__ rowe, const float* __restrict__ cole) {
    __shared__ float q0S[2][70];
    __shared__ float hidS[2][CHN];
    __shared__ int   indS[2];
    int t = threadIdx.x;
    int qg0 = blockIdx.x * 2;
    if (t < 2) indS[t] = g_ind[qg0 + t];
    __syncthreads();
    for (int idx = t; idx < 2 * 70; idx += 256) {
        int q = idx / 70, j = idx - q * 70;
        int b = (qg0 + q) >> 10;
        q0S[q][j] = preds[(b * 70 + j) * HWSZ + indS[q]];
    }
    #pragma unroll
    for (int q = 0; q < 2; q++) {
        int ind = indS[q];
        int xx = ind & 127, yy = ind >> 7;
        float pv = (t < 128) ? cole[xx * 128 + t] : rowe[yy * 128 + (t - 128)];
        g_qpos[(qg0 + q) * CHN + t] = pv;
    }
    __syncthreads();
    float acc[2] = {0.f, 0.f};
    for (int j = 0; j < 70; j++) {
        float w = W1[j * CHN + t];
        acc[0] += q0S[0][j] * w;
        acc[1] += q0S[1][j] * w;
    }
    float bb = b1[t];
    hidS[0][t] = gelu_tanh(acc[0] + bb);
    hidS[1][t] = gelu_tanh(acc[1] + bb);
    __syncthreads();
    float a2[2] = {0.f, 0.f};
    for (int i = 0; i < CHN; i++) {
        float w = W2[i * CHN + t];
        a2[0] += hidS[0][i] * w;
        a2[1] += hidS[1][i] * w;
    }
    float b2v = b2[t];
    g_q[(qg0 + 0) * CHN + t] = a2[0] + b2v;
    g_q[(qg0 + 1) * CHN + t] = a2[1] + b2v;
}

// ---------------- K4: standalone so/aw (layer 0 only) ----------------
__global__ __launch_bounds__(384) void k_soaw(
    const float* __restrict__ soW, const float* __restrict__ sob,
    const float* __restrict__ awW, const float* __restrict__ awb) {
    __shared__ __align__(16) float qnT[256 * TSB];
    int t = threadIdx.x;
    int qg0 = blockIdx.x * 8;

    for (int idx = t; idx < 2048; idx += 384) {
        int q = idx & 7, i = idx >> 3;
        qnT[i * TSB + q] = g_q[(qg0 + q) * CHN + i] + g_qpos[(qg0 + q) * CHN + i];
    }
    __syncthreads();

    if (t < 256) {
        ull acc2[4];
        #pragma unroll
        for (int p = 0; p < 4; p++) acc2[p] = pk2(0.f, 0.f);
        #pragma unroll 4
        for (int i = 0; i < 256; i++) {
            float w = soW[i * CHN + t];
            ull w2 = pk2(w, w);
            const ulonglong2 A0 = *(const ulonglong2*)&qnT[i * TSB + 0];
            const ulonglong2 A1 = *(const ulonglong2*)&qnT[i * TSB + 4];
            acc2[0] = fma2(A0.x, w2, acc2[0]);
            acc2[1] = fma2(A0.y, w2, acc2[1]);
            acc2[2] = fma2(A1.x, w2, acc2[2]);
            acc2[3] = fma2(A1.y, w2, acc2[3]);
        }
        float sbv = sob[t];
        #pragma unroll
        for (int p = 0; p < 4; p++) {
            float lo, hi;
            upk2(acc2[p], lo, hi);
            g_so[(qg0 + 2 * p) * CHN + t]     = lo + sbv;
            g_so[(qg0 + 2 * p + 1) * CHN + t] = hi + sbv;
        }
    } else {
        int c = t - 256;
        ull acc2[4];
        #pragma unroll
        for (int p = 0; p < 4; p++) acc2[p] = pk2(0.f, 0.f);
        #pragma unroll 4
        for (int i = 0; i < 256; i++) {
            float w = awW[i * 128 + c];
            ull w2 = pk2(w, w);
            const ulonglong2 A0 = *(const ulonglong2*)&qnT[i * TSB + 0];
            const ulonglong2 A1 = *(const ulonglong2*)&qnT[i * TSB + 4];
            acc2[0] = fma2(A0.x, w2, acc2[0]);
            acc2[1] = fma2(A0.y, w2, acc2[1]);
            acc2[2] = fma2(A1.x, w2, acc2[2]);
            acc2[3] = fma2(A1.y, w2, acc2[3]);
        }
        float ab = awb[c];
        float av[8];
        #pragma unroll
        for (int p = 0; p < 4; p++) {
            upk2(acc2[p], av[2 * p], av[2 * p + 1]);
            av[2 * p] += ab; av[2 * p + 1] += ab;
        }
        #pragma unroll
        for (int q = 0; q < 8; q++) {
            float vv = av[q];
            float m = vv;
            #pragma unroll
            for (int o = 8; o > 0; o >>= 1)
                m = fmaxf(m, __shfl_xor_sync(0xffffffffu, m, o, 16));
            float e = expf(vv - m);
            float s = e;
            #pragma unroll
            for (int o = 8; o > 0; o >>= 1)
                s += __shfl_xor_sync(0xffffffffu, s, o, 16);
            g_aw[(qg0 + q) * 128 + c] = e / s;
        }
    }
}

// ---------------- K5: fused per-layer megakernel: gather + vp + op + LN1 + FFN + LN2 (+next soaw) ----------------
__device__ __forceinline__ void ln4h(float v[4], float* redA, float* redB,
                                     float* mu, float* rs,
                                     const float* g, const float* b,
                                     int ch, int grp, int t) {
    int w = (t >> 5) & 7;
    int ln = t & 31;
    #pragma unroll
    for (int q = 0; q < 4; q++) {
        float s = v[q], s2 = v[q] * v[q];
        #pragma unroll
        for (int o = 16; o > 0; o >>= 1) {
            s  += __shfl_xor_sync(0xffffffffu, s, o);
            s2 += __shfl_xor_sync(0xffffffffu, s2, o);
        }
        if (ln == 0) { redA[(grp * 4 + q) * 8 + w] = s; redB[(grp * 4 + q) * 8 + w] = s2; }
    }
    __syncthreads();
    if (t < 8) {
        float s = 0.f, s2 = 0.f;
        #pragma unroll
        for (int k = 0; k < 8; k++) { s += redA[t * 8 + k]; s2 += redB[t * 8 + k]; }
        float m = s * (1.f / 256.f);
        mu[t] = m;
        rs[t] = rsqrtf(s2 * (1.f / 256.f) - m * m + 1e-5f);
    }
    __syncthreads();
    float gg = g[ch], bb = b[ch];
    #pragma unroll
    for (int q = 0; q < 4; q++)
        v[q] = (v[q] - mu[grp * 4 + q]) * rs[grp * 4 + q] * gg + bb;
}

__global__ __launch_bounds__(512) void k_layer(
    const float* __restrict__ vpW, const float* __restrict__ vpb,
    const float* __restrict__ opW, const float* __restrict__ opb,
    const float* __restrict__ g1, const float* __restrict__ b1,
    const float* __restrict__ W1, const float* __restrict__ fb1,
    const float* __restrict__ W2, const float* __restrict__ fb2,
    const float* __restrict__ g2, const float* __restrict__ b2,
    const float* __restrict__ soWn, const float* __restrict__ sobn,
    const float* __restrict__ awWn, const float* __restrict__ awbn,
    int has_next) {
    extern __shared__ __align__(16) unsigned char smraw[];
    __half* aggS = (__half*)smraw;                 // 8q x 8h x 256ch halves (32768 B)
    float*  U    = (float*)(smraw + 32768);        // 36864 B union region
    int*    hkey  = (int*)U;                       // [2][256]
    int*    list  = (int*)(U + 512);               // [2][256]
    float*  hcoef = U + 1024;                      // [2][256*8]
    float*  coefC = U + 5120;                      // [2][256*8]
    float*  bufT  = U;                             // post-gather alias (3072 floats)
    float*  qST   = U + 3072;                      // post-gather alias (3072 floats)
    __shared__ float redA[8 * 8], redB[8 * 8];
    __shared__ float mu[8], rs[8];
    __shared__ float bwS[64];
    __shared__ int   cnt2[2];

    int t = threadIdx.x;
    int ch = t & 255;
    int grp = t >> 8;            // 0 / 1
    int qb = grp * 4;
    int qg0 = blockIdx.x * 8;
    int h = ch >> 5;

    // ================= gather: 4 passes x 2 concurrent queries =================
    for (int pass = 0; pass < 4; pass++) {
        int qi = 2 * pass + grp;          // block-local query 0..7
        int kq = qg0 + qi;
        int bb = kq >> 10;
        int tt = ch;
        // clear this half's hash
        hkey[grp * 256 + tt] = -1;
        *(float4*)&hcoef[grp * 2048 + tt * 8]     = make_float4(0.f, 0.f, 0.f, 0.f);
        *(float4*)&hcoef[grp * 2048 + tt * 8 + 4] = make_float4(0.f, 0.f, 0.f, 0.f);
        if (tt == 0) cnt2[grp] = 0;
        __syncthreads();

        if (tt < 128) {
            int ind = g_ind[kq];
            int hh = tt >> 4;
            int f = (tt >> 2) & 3;
            float offx = g_so[kq * CHN + 2 * tt];
            float offy = g_so[kq * CHN + 2 * tt + 1];
            float aw = g_aw[kq * 128 + tt];
            float xs = (float)(ind & 127) + offx;
            float ys = (float)(ind >> 7) + offy;
            float xf = floorf(xs), yf = floorf(ys);
            int x0 = (int)xf, y0 = (int)yf;
            float wx1 = xs - xf, wy1 = ys - yf;
            float wx0 = 1.f - wx1, wy0 = 1.f - wy1;
            int cxs[4] = {x0, x0 + 1, x0, x0 + 1};
            int cys[4] = {y0, y0, y0 + 1, y0 + 1};
            float cw[4] = {wx0 * wy0, wx1 * wy0, wx0 * wy1, wx1 * wy1};
            int base = (bb * 4 + f) * HWSZ;
            float evs = 0.f;
            #pragma unroll
            for (int c = 0; c < 4; c++) {
                bool v = (cxs[c] >= 0) & (cxs[c] < 128) & (cys[c] >= 0) & (cys[c] < 128);
                if (v) {
                    int key = base + cys[c] * 128 + cxs[c];
                    float cf = aw * cw[c];
                    evs += cf;
                    unsigned s = ((unsigned)key * 2654435761u) >> 24;
                    while (true) {
                        int prev = atomicCAS(&hkey[grp * 256 + s], -1, key);
                        if (prev == -1 || prev == key) break;
                        s = (s + 1) & (HSLOTS - 1);
                    }
                    atomicAdd(&hcoef[grp * 2048 + s * 8 + hh], cf);
                }
            }
            #pragma unroll
            for (int o = 8; o > 0; o >>= 1)
                evs += __shfl_xor_sync(0xffffffffu, evs, o, 16);
            if ((tt & 15) == 0) bwS[qi * 8 + hh] = evs;
        }
        __syncthreads();

        // compact this half's occupied slots
        {
            int key = hkey[grp * 256 + tt];
            if (key >= 0) {
                int pos = atomicAdd(&cnt2[grp], 1);
                list[grp * 256 + pos] = key;
                *(float4*)&coefC[grp * 2048 + pos * 8]     = *(const float4*)&hcoef[grp * 2048 + tt * 8];
                *(float4*)&coefC[grp * 2048 + pos * 8 + 4] = *(const float4*)&hcoef[grp * 2048 + tt * 8 + 4];
            }
        }
        __syncthreads();
        int D = cnt2[grp];

        // aggregate: thread tt = channel, query qi; MLP=4
        ull acc2[4];
        #pragma unroll
        for (int p = 0; p < 4; p++) acc2[p] = pk2(0.f, 0.f);
        int d = 0;
        for (; d + 4 <= D; d += 4) {
            unsigned short r0 = g_val[(size_t)list[grp * 256 + d + 0] * CHN + tt];
            unsigned short r1 = g_val[(size_t)list[grp * 256 + d + 1] * CHN + tt];
            unsigned short r2 = g_val[(size_t)list[grp * 256 + d + 2] * CHN + tt];
            unsigned short r3 = g_val[(size_t)list[grp * 256 + d + 3] * CHN + tt];
            #pragma unroll
            for (int u = 0; u < 4; u++) {
                unsigned short rr = (u == 0) ? r0 : (u == 1) ? r1 : (u == 2) ? r2 : r3;
                float vv = h2f(rr);
                ull v2p = pk2(vv, vv);
                const ulonglong2 C0 = *(const ulonglong2*)&coefC[grp * 2048 + (d + u) * 8];
                const ulonglong2 C1 = *(const ulonglong2*)&coefC[grp * 2048 + (d + u) * 8 + 4];
                acc2[0] = fma2(C0.x, v2p, acc2[0]);
                acc2[1] = fma2(C0.y, v2p, acc2[1]);
                acc2[2] = fma2(C1.x, v2p, acc2[2]);
                acc2[3] = fma2(C1.y, v2p, acc2[3]);
            }
        }
        for (; d < D; d++) {
            unsigned short rr = g_val[(size_t)list[grp * 256 + d] * CHN + tt];
            float vv = h2f(rr);
            ull v2p = pk2(vv, vv);
            const ulonglong2 C0 = *(const ulonglong2*)&coefC[grp * 2048 + d * 8];
            const ulonglong2 C1 = *(const ulonglong2*)&coefC[grp * 2048 + d * 8 + 4];
            acc2[0] = fma2(C0.x, v2p, acc2[0]);
            acc2[1] = fma2(C0.y, v2p, acc2[1]);
            acc2[2] = fma2(C1.x, v2p, acc2[2]);
            acc2[3] = fma2(C1.y, v2p, acc2[3]);
        }
        #pragma unroll
        for (int p = 0; p < 4; p++) {
            float lo, hi;
            upk2(acc2[p], lo, hi);
            aggS[(qi * 8 + 2 * p) * 256 + tt]     = __float2half(lo);
            aggS[(qi * 8 + 2 * p + 1) * 256 + tt] = __float2half(hi);
        }
        __syncthreads();   // hash reuse next pass; final pass: agg visible for vp
    }

    float v[4];

    // ---- vp: agg (fp16 smem, broadcast) x vpW ----
    {
        ull a2v[4];
        #pragma unroll
        for (int q = 0; q < 4; q++) a2v[q] = pk2(0.f, 0.f);
        for (int i4 = 0; i4 < 64; i4++) {
            float w0 = vpW[(4 * i4 + 0) * CHN + ch];
            float w1 = vpW[(4 * i4 + 1) * CHN + ch];
            float w2 = vpW[(4 * i4 + 2) * CHN + ch];
            float w3 = vpW[(4 * i4 + 3) * CHN + ch];
            ull w01 = pk2(w0, w1), w23 = pk2(w2, w3);
            #pragma unroll
            for (int q = 0; q < 4; q++) {
                const __half2* ap = (const __half2*)&aggS[((qb + q) * 8 + h) * 256 + 4 * i4];
                float2 lo2 = __half22float2(ap[0]);
                float2 hi2 = __half22float2(ap[1]);
                a2v[q] = fma2(pk2(lo2.x, lo2.y), w01, a2v[q]);
                a2v[q] = fma2(pk2(hi2.x, hi2.y), w23, a2v[q]);
            }
        }
        float vb = vpb[ch];
        float4 o;
        float lo, hi;
        upk2(a2v[0], lo, hi); o.x = lo + hi + bwS[(qb + 0) * 8 + h] * vb;
        upk2(a2v[1], lo, hi); o.y = lo + hi + bwS[(qb + 1) * 8 + h] * vb;
        upk2(a2v[2], lo, hi); o.z = lo + hi + bwS[(qb + 2) * 8 + h] * vb;
        upk2(a2v[3], lo, hi); o.w = lo + hi + bwS[(qb + 3) * 8 + h] * vb;
        __syncthreads();   // aggS reads done before bufT (aliased region is separate; this guards hash region only)
        *(float4*)&bufT[ch * TSB + qb] = o;
    }
    __syncthreads();

    // ---- op ----
    ull acc2[2];
    acc2[0] = pk2(g_q[(qg0 + qb + 0) * CHN + ch], g_q[(qg0 + qb + 1) * CHN + ch]);
    acc2[1] = pk2(g_q[(qg0 + qb + 2) * CHN + ch], g_q[(qg0 + qb + 3) * CHN + ch]);
    #pragma unroll 4
    for (int i = 0; i < 256; i++) {
        float w = opW[i * CHN + ch];
        ull w2 = pk2(w, w);
        const ulonglong2 A0 = *(const ulonglong2*)&bufT[i * TSB + qb];
        acc2[0] = fma2(A0.x, w2, acc2[0]);
        acc2[1] = fma2(A0.y, w2, acc2[1]);
    }
    {
        float ob = opb[ch];
        upk2(acc2[0], v[0], v[1]);
        upk2(acc2[1], v[2], v[3]);
        #pragma unroll
        for (int q = 0; q < 4; q++) v[q] += ob;
    }

    // ---- LN1 ----
    ln4h(v, redA, redB, mu, rs, g1, b1, ch, grp, t);
    *(float4*)&qST[ch * TSB + qb] = make_float4(v[0], v[1], v[2], v[3]);
    __syncthreads();

    // ---- FFN ----
    ull o2[2];
    o2[0] = pk2(0.f, 0.f); o2[1] = pk2(0.f, 0.f);
    for (int chunk = 0; chunk < 4; chunk++) {
        ull h2[2];
        h2[0] = pk2(0.f, 0.f); h2[1] = pk2(0.f, 0.f);
        int j = chunk * CHN + ch;
        #pragma unroll 4
        for (int i = 0; i < 256; i++) {
            float w = W1[i * 1024 + j];
            ull w2 = pk2(w, w);
            const ulonglong2 A0 = *(const ulonglong2*)&qST[i * TSB + qb];
            h2[0] = fma2(A0.x, w2, h2[0]);
            h2[1] = fma2(A0.y, w2, h2[1]);
        }
        float bj = fb1[j];
        {
            float a, b_, c, d_;
            upk2(h2[0], a, b_);
            upk2(h2[1], c, d_);
            *(float4*)&bufT[ch * TSB + qb] = make_float4(
                fmaxf(a + bj, 0.f), fmaxf(b_ + bj, 0.f),
                fmaxf(c + bj, 0.f), fmaxf(d_ + bj, 0.f));
        }
        __syncthreads();
        #pragma unroll 4
        for (int i = 0; i < 256; i++) {
            float w = W2[(chunk * CHN + i) * CHN + ch];
            ull w2 = pk2(w, w);
            const ulonglong2 A0 = *(const ulonglong2*)&bufT[i * TSB + qb];
            o2[0] = fma2(A0.x, w2, o2[0]);
            o2[1] = fma2(A0.y, w2, o2[1]);
        }
        __syncthreads();
    }
    {
        float fb = fb2[ch];
        upk2(o2[0], v[0], v[1]);
        upk2(o2[1], v[2], v[3]);
        #pragma unroll
        for (int q = 0; q < 4; q++) v[q] += qST[ch * TSB + qb + q] + fb;
    }

    // ---- LN2 ----
    ln4h(v, redA, redB, mu, rs, g2, b2, ch, grp, t);
    #pragma unroll
    for (int q = 0; q < 4; q++) g_q[(qg0 + qb + q) * CHN + ch] = v[q];

    // ---- fused next-layer so/aw ----
    if (has_next) {
        #pragma unroll
        for (int q = 0; q < 4; q++)
            bufT[ch * TSB + qb + q] = v[q] + g_qpos[(qg0 + qb + q) * CHN + ch];
        __syncthreads();

        if (t < 256) {
            ull s2[4];
            #pragma unroll
            for (int p = 0; p < 4; p++) s2[p] = pk2(0.f, 0.f);
            #pragma unroll 4
            for (int i = 0; i < 256; i++) {
                float w = soWn[i * CHN + t];
                ull w2 = pk2(w, w);
                const ulonglong2 A0 = *(const ulonglong2*)&bufT[i * TSB + 0];
                const ulonglong2 A1 = *(const ulonglong2*)&bufT[i * TSB + 4];
                s2[0] = fma2(A0.x, w2, s2[0]);
                s2[1] = fma2(A0.y, w2, s2[1]);
                s2[2] = fma2(A1.x, w2, s2[2]);
                s2[3] = fma2(A1.y, w2, s2[3]);
            }
            float sbv = sobn[t];
            #pragma unroll
            for (int p = 0; p < 4; p++) {
                float lo, hi;
                upk2(s2[p], lo, hi);
                g_so[(qg0 + 2 * p) * CHN + t]     = lo + sbv;
                g_so[(qg0 + 2 * p + 1) * CHN + t] = hi + sbv;
            }
        } else if (t < 384) {
            int c = t - 256;
            ull s2[4];
            #pragma unroll
            for (int p = 0; p < 4; p++) s2[p] = pk2(0.f, 0.f);
            #pragma unroll 4
            for (int i = 0; i < 256; i++) {
                float w = awWn[i * 128 + c];
                ull w2 = pk2(w, w);
                const ulonglong2 A0 = *(const ulonglong2*)&bufT[i * TSB + 0];
                const ulonglong2 A1 = *(const ulonglong2*)&bufT[i * TSB + 4];
                s2[0] = fma2(A0.x, w2, s2[0]);
                s2[1] = fma2(A0.y, w2, s2[1]);
                s2[2] = fma2(A1.x, w2, s2[2]);
                s2[3] = fma2(A1.y, w2, s2[3]);
            }
            float ab = awbn[c];
            float av[8];
            #pragma unroll
            for (int p = 0; p < 4; p++) {
                upk2(s2[p], av[2 * p], av[2 * p + 1]);
                av[2 * p] += ab; av[2 * p + 1] += ab;
            }
            #pragma unroll
            for (int q = 0; q < 8; q++) {
                float vv = av[q];
                float m = vv;
                #pragma unroll
                for (int o = 8; o > 0; o >>= 1)
                    m = fmaxf(m, __shfl_xor_sync(0xffffffffu, m, o, 16));
                float e = expf(vv - m);
                float s = e;
                #pragma unroll
                for (int o = 8; o > 0; o >>= 1)
                    s += __shfl_xor_sync(0xffffffffu, s, o, 16);
                g_aw[(qg0 + q) * 128 + c] = e / s;
            }
        }
    }
}

// ---------------- K7/K8: zero-fill output, scatter queries ----------------
__global__ void k_zero(float4* __restrict__ out) {
    out[(size_t)blockIdx.x * 256 + threadIdx.x] = make_float4(0.f, 0.f, 0.f, 0.f);
}

__global__ void k_scatter(float* __restrict__ out) {
    int k = blockIdx.x, t = threadIdx.x;
    int b = k >> 10;
    int ind = g_ind[k];
    out[(b * CHN + t) * HWSZ + ind] = g_q[k * CHN + t];
}

// ---------------- launch (single stream) ----------------
#define LAYER_SMEM (32768 + 36864)

extern "C" void kernel_launch(void* const* d_in, const int* in_sizes, int n_in,
                              void* d_out, int out_size) {
    const float* x    = (const float*)d_in[0];
    const float* preds= (const float*)d_in[1];
    const float* hm   = (const float*)d_in[2];
    const float* mW1  = (const float*)d_in[3];
    const float* mb1  = (const float*)d_in[4];
    const float* mW2  = (const float*)d_in[5];
    const float* mb2  = (const float*)d_in[6];
    const float* tp   = (const float*)d_in[7];
    const float* rowe = (const float*)d_in[8];
    const float* cole = (const float*)d_in[9];
    const float* soW  = (const float*)d_in[10];
    const float* sob  = (const float*)d_in[11];
    const float* awW  = (const float*)d_in[12];
    const float* awb  = (const float*)d_in[13];
    const float* vpW  = (const float*)d_in[14];
    const float* vpb  = (const float*)d_in[15];
    const float* opW  = (const float*)d_in[16];
    const float* opb  = (const float*)d_in[17];
    const float* l1g  = (const float*)d_in[18];
    const float* l1b  = (const float*)d_in[19];
    const float* fW1  = (const float*)d_in[20];
    const float* fb1  = (const float*)d_in[21];
    const float* fW2  = (const float*)d_in[22];
    const float* fb2  = (const float*)d_in[23];
    const float* l2g  = (const float*)d_in[24];
    const float* l2b  = (const float*)d_in[25];
    float* out = (float*)d_out;

    static int inited = 0;
    if (!inited) {
        cudaFuncSetAttribute(k_layer, cudaFuncAttributeMaxDynamicSharedMemorySize, LAYER_SMEM);
        inited = 1;
    }

    k_transpose<<<dim3(4, 8, 1024), 256>>>(x, tp);
    k_score<<<32, 1024>>>(hm);
    k_topk<<<2, 1024>>>();
    k_qinit<<<1024, 256>>>(preds, mW1, mb1, mW2, mb2, rowe, cole);
    k_soaw<<<256, 384>>>(soW, sob, awW, awb);
    for (int l = 0; l < 3; l++) {
        int nl = (l < 2) ? l + 1 : l;
        k_layer<<<256, 512, LAYER_SMEM>>>(
            vpW + l * 65536, vpb + l * 256,
            opW + l * 65536, opb + l * 256,
            l1g + l * 256, l1b + l * 256,
            fW1 + l * 262144, fb1 + l * 1024,
            fW2 + l * 262144, fb2 + l * 256,
            l2g + l * 256, l2b + l * 256,
            soW + nl * 65536, sob + nl * 256,
            awW + nl * 32768, awb + nl * 128,
            (l < 2) ? 1 : 0);
    }
    k_zero<<<8192, 256>>>((float4*)out);
    k_scatter<<<2048, 256>>>(out);
}

// round 17
// speedup vs baseline: 1.4013x; 1.4013x over previous
#include <cuda_runtime.h>
#include <cuda_fp16.h>
#include <math.h>

#define HWSZ 16384
#define CHN  256
#define KQ   1024
#define NQ   2048
#define HSLOTS 256
#define TSB 12   // transposed activation stride (8 q + 4 pad), 48B = 16B-aligned rows

// ---------------- device scratch (static, allocation-free) ----------------
__device__ unsigned short g_val[(size_t)2 * 4 * HWSZ * CHN];  // fp16 [b*4+f][y][x][c], +time_pos
__device__ unsigned g_keys[2 * HWSZ];
__device__ int      g_ind[NQ];
__device__ float    g_q[NQ * CHN];
__device__ float    g_qpos[NQ * CHN];
__device__ float    g_so[NQ * CHN];
__device__ float    g_aw[NQ * 128];
__device__ float    g_agg[(size_t)NQ * 8 * CHN];   // [q][h][ch]
__device__ float    g_bw[NQ * 8];

// ---------------- f32x2 packed helpers ----------------
typedef unsigned long long ull;
__device__ __forceinline__ ull pk2(float x, float y) {
    ull r;
    asm("mov.b64 %0, {%1, %2};" : "=l"(r) : "f"(x), "f"(y));
    return r;
}
__device__ __forceinline__ void upk2(ull v, float& x, float& y) {
    asm("mov.b64 {%0, %1}, %2;" : "=f"(x), "=f"(y) : "l"(v));
}
__device__ __forceinline__ ull fma2(ull a, ull b, ull c) {
    ull d;
    asm("fma.rn.f32x2 %0, %1, %2, %3;" : "=l"(d) : "l"(a), "l"(b), "l"(c));
    return d;
}
__device__ __forceinline__ unsigned h2pack(float a, float b) {
    __half2 h = __floats2half2_rn(a, b);
    return *(unsigned*)&h;
}
__device__ __forceinline__ float h2f(unsigned short r) {
    __half h = *(__half*)&r;
    return __half2float(h);
}

__device__ __forceinline__ float gelu_tanh(float v) {
    float c = 0.7978845608028654f * (v + 0.044715f * v * v * v);
    return 0.5f * v * (1.0f + tanhf(c));
}

// ---------------- K1: transpose x -> g_val fp16 (+time_pos) ----------------
__global__ __launch_bounds__(256) void k_transpose(const float* __restrict__ x,
                                                   const float* __restrict__ tp) {
    __shared__ float tile[32][33];
    int xt = blockIdx.x * 32;
    int ct = blockIdx.y * 32;
    int z  = blockIdx.z;
    int y  = z & 127;
    int bf = z >> 7;
    int f  = bf & 3;
    int tid = threadIdx.x;

    {
        int c = tid >> 3, xq = tid & 7;
        const float4 v = *(const float4*)&x[((size_t)(bf * CHN + ct + c) * 128 + y) * 128 + xt + xq * 4];
        tile[c][xq * 4 + 0] = v.x;
        tile[c][xq * 4 + 1] = v.y;
        tile[c][xq * 4 + 2] = v.z;
        tile[c][xq * 4 + 3] = v.w;
    }
    __syncthreads();
    {
        int row = tid >> 3, quad = tid & 7;
        const float4 tq = *(const float4*)&tp[f * CHN + ct + quad * 4];
        float o0 = tile[quad * 4 + 0][row] + tq.x;
        float o1 = tile[quad * 4 + 1][row] + tq.y;
        float o2 = tile[quad * 4 + 2][row] + tq.z;
        float o3 = tile[quad * 4 + 3][row] + tq.w;
        uint2 packed = make_uint2(h2pack(o0, o1), h2pack(o2, o3));
        *(uint2*)&g_val[((size_t)(bf * 128 + y) * 128 + xt + row) * CHN + ct + quad * 4] = packed;
    }
}

// ---------------- K2a: channel-max score -> orderable keys ----------------
__global__ __launch_bounds__(1024) void k_score(const float* __restrict__ hm) {
    int i = blockIdx.x * 1024 + threadIdx.x;
    int b = i >> 14, cell = i & (HWSZ - 1);
    const float* hb = hm + (size_t)b * 10 * HWSZ + cell;
    float m = hb[0];
    #pragma unroll
    for (int c = 1; c < 10; c++) m = fmaxf(m, hb[c * HWSZ]);
    unsigned u = __float_as_uint(m);
    u = (u & 0x80000000u) ? ~u : (u | 0x80000000u);
    g_keys[i] = u;
}

// ---------------- K2b: radix top-1024 per batch ----------------
__global__ __launch_bounds__(1024) void k_topk() {
    int b = blockIdx.x, t = threadIdx.x;
    __shared__ unsigned hist[256];
    __shared__ unsigned suf[256];
    __shared__ unsigned sh[4];

    unsigned prefix = 0, r = KQ;
    for (int byte = 3; byte >= 0; byte--) {
        if (t < 256) hist[t] = 0;
        __syncthreads();
        int sh8 = byte * 8;
        unsigned pm = (byte == 3) ? 0u : (0xFFFFFFFFu << (8 * (byte + 1)));
        for (int i = t; i < HWSZ; i += 1024) {
            unsigned k = g_keys[b * HWSZ + i];
            if ((k & pm) == (prefix & pm)) atomicAdd(&hist[(k >> sh8) & 255u], 1u);
        }
        __syncthreads();
        if (t < 256) suf[t] = hist[t];
        __syncthreads();
        #pragma unroll
        for (int off = 1; off < 256; off <<= 1) {
            unsigned add = 0;
            if (t < 256 && t + off < 256) add = suf[t + off];
            __syncthreads();
            if (t < 256) suf[t] += add;
            __syncthreads();
        }
        if (t < 256) {
            unsigned nxt = (t == 255) ? 0u : suf[t + 1];
            if (suf[t] >= r && nxt < r) { sh[0] = (unsigned)t; sh[1] = r - nxt; }
        }
        __syncthreads();
        prefix |= sh[0] << sh8;
        r = sh[1];
        __syncthreads();
    }
    unsigned T = prefix;
    if (t == 0) { sh[2] = 0; sh[3] = 0; }
    __syncthreads();
    for (int i = t; i < HWSZ; i += 1024)
        if (g_keys[b * HWSZ + i] > T) atomicAdd(&sh[2], 1u);
    __syncthreads();
    unsigned cgt = sh[2];
    unsigned neq = KQ - cgt;
    __syncthreads();
    if (t == 0) sh[2] = 0;
    __syncthreads();
    for (int i = t; i < HWSZ; i += 1024) {
        unsigned k = g_keys[b * HWSZ + i];
        if (k > T) {
            unsigned s = atomicAdd(&sh[2], 1u);
            g_ind[b * KQ + s] = i;
        } else if (k == T) {
            unsigned e = atomicAdd(&sh[3], 1u);
            if (e < neq) g_ind[b * KQ + cgt + e] = i;
        }
    }
}

// ---------------- K3: query-init MLP + positional embed gather (2 q/block) ----------------
__global__ __launch_bounds__(256) void k_qinit(
    const float* __restrict__ preds,
    const float* __restrict__ W1, const float* __restrict__ b1,
    const float* __restrict__ W2, const float* __restrict__ b2,
    const float* __restrict__ rowe, const float* __restrict__ cole) {
    __shared__ float q0S[2][70];
    __shared__ float hidS[2][CHN];
    __shared__ int   indS[2];
    int t = threadIdx.x;
    int qg0 = blockIdx.x * 2;
    if (t < 2) indS[t] = g_ind[qg0 + t];
    __syncthreads();
    for (int idx = t; idx < 2 * 70; idx += 256) {
        int q = idx / 70, j = idx - q * 70;
        int b = (qg0 + q) >> 10;
        q0S[q][j] = preds[(b * 70 + j) * HWSZ + indS[q]];
    }
    #pragma unroll
    for (int q = 0; q < 2; q++) {
        int ind = indS[q];
        int xx = ind & 127, yy = ind >> 7;
        float pv = (t < 128) ? cole[xx * 128 + t] : rowe[yy * 128 + (t - 128)];
        g_qpos[(qg0 + q) * CHN + t] = pv;
    }
    __syncthreads();
    float acc[2] = {0.f, 0.f};
    for (int j = 0; j < 70; j++) {
        float w = W1[j * CHN + t];
        acc[0] += q0S[0][j] * w;
        acc[1] += q0S[1][j] * w;
    }
    float bb = b1[t];
    hidS[0][t] = gelu_tanh(acc[0] + bb);
    hidS[1][t] = gelu_tanh(acc[1] + bb);
    __syncthreads();
    float a2[2] = {0.f, 0.f};
    for (int i = 0; i < CHN; i++) {
        float w = W2[i * CHN + t];
        a2[0] += hidS[0][i] * w;
        a2[1] += hidS[1][i] * w;
    }
    float b2v = b2[t];
    g_q[(qg0 + 0) * CHN + t] = a2[0] + b2v;
    g_q[(qg0 + 1) * CHN + t] = a2[1] + b2v;
}

// ---------------- K4: standalone so/aw (layer 0, per-half) ----------------
__global__ __launch_bounds__(384) void k_soaw(
    int qbase,
    const float* __restrict__ soW, const float* __restrict__ sob,
    const float* __restrict__ awW, const float* __restrict__ awb) {
    __shared__ __align__(16) float qnT[256 * TSB];
    int t = threadIdx.x;
    int qg0 = qbase + blockIdx.x * 8;

    for (int idx = t; idx < 2048; idx += 384) {
        int q = idx & 7, i = idx >> 3;
        qnT[i * TSB + q] = g_q[(qg0 + q) * CHN + i] + g_qpos[(qg0 + q) * CHN + i];
    }
    __syncthreads();

    if (t < 256) {
        ull acc2[4];
        #pragma unroll
        for (int p = 0; p < 4; p++) acc2[p] = pk2(0.f, 0.f);
        #pragma unroll 4
        for (int i = 0; i < 256; i++) {
            float w = soW[i * CHN + t];
            ull w2 = pk2(w, w);
            const ulonglong2 A0 = *(const ulonglong2*)&qnT[i * TSB + 0];
            const ulonglong2 A1 = *(const ulonglong2*)&qnT[i * TSB + 4];
            acc2[0] = fma2(A0.x, w2, acc2[0]);
            acc2[1] = fma2(A0.y, w2, acc2[1]);
            acc2[2] = fma2(A1.x, w2, acc2[2]);
            acc2[3] = fma2(A1.y, w2, acc2[3]);
        }
        float sbv = sob[t];
        #pragma unroll
        for (int p = 0; p < 4; p++) {
            float lo, hi;
            upk2(acc2[p], lo, hi);
            g_so[(qg0 + 2 * p) * CHN + t]     = lo + sbv;
            g_so[(qg0 + 2 * p + 1) * CHN + t] = hi + sbv;
        }
    } else {
        int c = t - 256;
        ull acc2[4];
        #pragma unroll
        for (int p = 0; p < 4; p++) acc2[p] = pk2(0.f, 0.f);
        #pragma unroll 4
        for (int i = 0; i < 256; i++) {
            float w = awW[i * 128 + c];
            ull w2 = pk2(w, w);
            const ulonglong2 A0 = *(const ulonglong2*)&qnT[i * TSB + 0];
            const ulonglong2 A1 = *(const ulonglong2*)&qnT[i * TSB + 4];
            acc2[0] = fma2(A0.x, w2, acc2[0]);
            acc2[1] = fma2(A0.y, w2, acc2[1]);
            acc2[2] = fma2(A1.x, w2, acc2[2]);
            acc2[3] = fma2(A1.y, w2, acc2[3]);
        }
        float ab = awb[c];
        float av[8];
        #pragma unroll
        for (int p = 0; p < 4; p++) {
            upk2(acc2[p], av[2 * p], av[2 * p + 1]);
            av[2 * p] += ab; av[2 * p + 1] += ab;
        }
        #pragma unroll
        for (int q = 0; q < 8; q++) {
            float vv = av[q];
            float m = vv;
            #pragma unroll
            for (int o = 8; o > 0; o >>= 1)
                m = fmaxf(m, __shfl_xor_sync(0xffffffffu, m, o, 16));
            float e = expf(vv - m);
            float s = e;
            #pragma unroll
            for (int o = 8; o > 0; o >>= 1)
                s += __shfl_xor_sync(0xffffffffu, s, o, 16);
            g_aw[(qg0 + q) * 128 + c] = e / s;
        }
    }
}

// ---------------- K5: per-query dedup gather-aggregate (fp16 values, per-half) ----------------
__global__ __launch_bounds__(256) void k_gather(int qbase) {
    __shared__ __align__(16) float hcoef[HSLOTS * 8];
    __shared__ __align__(16) float coefC[HSLOTS * 8];
    __shared__ int hkey[HSLOTS];
    __shared__ int cellList[HSLOTS];
    __shared__ int cntS;

    int t = threadIdx.x;
    int kq = qbase + blockIdx.x;
    int b = kq >> 10;

    hkey[t] = -1;
    ((float4*)hcoef)[t * 2]     = make_float4(0.f, 0.f, 0.f, 0.f);
    ((float4*)hcoef)[t * 2 + 1] = make_float4(0.f, 0.f, 0.f, 0.f);
    if (t == 0) cntS = 0;
    __syncthreads();

    if (t < 128) {
        int ind = g_ind[kq];
        int h = t >> 4;
        int f = (t >> 2) & 3;
        float offx = g_so[kq * CHN + 2 * t];
        float offy = g_so[kq * CHN + 2 * t + 1];
        float aw = g_aw[kq * 128 + t];
        float xs = (float)(ind & 127) + offx;
        float ys = (float)(ind >> 7) + offy;
        float xf = floorf(xs), yf = floorf(ys);
        int x0 = (int)xf, y0 = (int)yf;
        float wx1 = xs - xf, wy1 = ys - yf;
        float wx0 = 1.f - wx1, wy0 = 1.f - wy1;
        int cxs[4] = {x0, x0 + 1, x0, x0 + 1};
        int cys[4] = {y0, y0, y0 + 1, y0 + 1};
        float cw[4] = {wx0 * wy0, wx1 * wy0, wx0 * wy1, wx1 * wy1};
        int base = (b * 4 + f) * HWSZ;
        float evs = 0.f;
        #pragma unroll
        for (int c = 0; c < 4; c++) {
            bool v = (cxs[c] >= 0) & (cxs[c] < 128) & (cys[c] >= 0) & (cys[c] < 128);
            if (v) {
                int key = base + cys[c] * 128 + cxs[c];
                float cf = aw * cw[c];
                evs += cf;
                unsigned s = ((unsigned)key * 2654435761u) >> 24;
                while (true) {
                    int prev = atomicCAS(&hkey[s], -1, key);
                    if (prev == -1 || prev == key) break;
                    s = (s + 1) & (HSLOTS - 1);
                }
                atomicAdd(&hcoef[s * 8 + h], cf);
            }
        }
        #pragma unroll
        for (int o = 8; o > 0; o >>= 1)
            evs += __shfl_xor_sync(0xffffffffu, evs, o, 16);
        if ((t & 15) == 0) g_bw[kq * 8 + h] = evs;
    }
    __syncthreads();

    {
        int key = hkey[t];
        if (key >= 0) {
            int pos = atomicAdd(&cntS, 1);
            cellList[pos] = key;
            ((float4*)coefC)[pos * 2]     = ((const float4*)hcoef)[t * 2];
            ((float4*)coefC)[pos * 2 + 1] = ((const float4*)hcoef)[t * 2 + 1];
        }
    }
    __syncthreads();
    int D = cntS;

    ull acc2[4];
    #pragma unroll
    for (int p = 0; p < 4; p++) acc2[p] = pk2(0.f, 0.f);
    int d = 0;
    for (; d + 4 <= D; d += 4) {
        unsigned short r0 = g_val[(size_t)cellList[d + 0] * CHN + t];
        unsigned short r1 = g_val[(size_t)cellList[d + 1] * CHN + t];
        unsigned short r2 = g_val[(size_t)cellList[d + 2] * CHN + t];
        unsigned short r3 = g_val[(size_t)cellList[d + 3] * CHN + t];
        #pragma unroll
        for (int u = 0; u < 4; u++) {
            unsigned short rr = (u == 0) ? r0 : (u == 1) ? r1 : (u == 2) ? r2 : r3;
            float vv = h2f(rr);
            ull v2p = pk2(vv, vv);
            const ulonglong2 C0 = *(const ulonglong2*)&coefC[(d + u) * 8];
            const ulonglong2 C1 = *(const ulonglong2*)&coefC[(d + u) * 8 + 4];
            acc2[0] = fma2(C0.x, v2p, acc2[0]);
            acc2[1] = fma2(C0.y, v2p, acc2[1]);
            acc2[2] = fma2(C1.x, v2p, acc2[2]);
            acc2[3] = fma2(C1.y, v2p, acc2[3]);
        }
    }
    for (; d < D; d++) {
        unsigned short rr = g_val[(size_t)cellList[d] * CHN + t];
        float vv = h2f(rr);
        ull v2p = pk2(vv, vv);
        const ulonglong2 C0 = *(const ulonglong2*)&coefC[d * 8];
        const ulonglong2 C1 = *(const ulonglong2*)&coefC[d * 8 + 4];
        acc2[0] = fma2(C0.x, v2p, acc2[0]);
        acc2[1] = fma2(C0.y, v2p, acc2[1]);
        acc2[2] = fma2(C1.x, v2p, acc2[2]);
        acc2[3] = fma2(C1.y, v2p, acc2[3]);
    }
    #pragma unroll
    for (int p = 0; p < 4; p++) {
        float lo, hi;
        upk2(acc2[p], lo, hi);
        g_agg[((size_t)kq * 8 + 2 * p) * CHN + t]     = lo;
        g_agg[((size_t)kq * 8 + 2 * p + 1) * CHN + t] = hi;
    }
}

// ---------------- K6: per-layer tail + fused next-layer soaw (per-half) ----------------
__device__ __forceinline__ void ln4h(float v[4], float* redA, float* redB,
                                     float* mu, float* rs,
                                     const float* g, const float* b,
                                     int ch, int grp, int t) {
    int w = (t >> 5) & 7;
    int ln = t & 31;
    #pragma unroll
    for (int q = 0; q < 4; q++) {
        float s = v[q], s2 = v[q] * v[q];
        #pragma unroll
        for (int o = 16; o > 0; o >>= 1) {
            s  += __shfl_xor_sync(0xffffffffu, s, o);
            s2 += __shfl_xor_sync(0xffffffffu, s2, o);
        }
        if (ln == 0) { redA[(grp * 4 + q) * 8 + w] = s; redB[(grp * 4 + q) * 8 + w] = s2; }
    }
    __syncthreads();
    if (t < 8) {
        float s = 0.f, s2 = 0.f;
        #pragma unroll
        for (int k = 0; k < 8; k++) { s += redA[t * 8 + k]; s2 += redB[t * 8 + k]; }
        float m = s * (1.f / 256.f);
        mu[t] = m;
        rs[t] = rsqrtf(s2 * (1.f / 256.f) - m * m + 1e-5f);
    }
    __syncthreads();
    float gg = g[ch], bb = b[ch];
    #pragma unroll
    for (int q = 0; q < 4; q++)
        v[q] = (v[q] - mu[grp * 4 + q]) * rs[grp * 4 + q] * gg + bb;
}

__global__ __launch_bounds__(512) void k_tail(
    int qbase,
    const float* __restrict__ vpW, const float* __restrict__ vpb,
    const float* __restrict__ opW, const float* __restrict__ opb,
    const float* __restrict__ g1, const float* __restrict__ b1,
    const float* __restrict__ W1, const float* __restrict__ fb1,
    const float* __restrict__ W2, const float* __restrict__ fb2,
    const float* __restrict__ g2, const float* __restrict__ b2,
    const float* __restrict__ soWn, const float* __restrict__ sobn,
    const float* __restrict__ awWn, const float* __restrict__ awbn,
    int has_next) {
    __shared__ __align__(16) float bufT[256 * TSB];
    __shared__ __align__(16) float qST[256 * TSB];
    __shared__ float redA[8 * 8], redB[8 * 8];
    __shared__ float mu[8], rs[8];
    int t = threadIdx.x;
    int ch = t & 255;
    int grp = t >> 8;
    int qb = grp * 4;
    int qg0 = qbase + blockIdx.x * 8;
    int h = ch >> 5;

    float v[4];

    // ---- vp: f32x2 over the reduction dim ----
    {
        ull a2v[4];
        #pragma unroll
        for (int q = 0; q < 4; q++) a2v[q] = pk2(0.f, 0.f);
        for (int i4 = 0; i4 < 64; i4++) {
            float w0 = vpW[(4 * i4 + 0) * CHN + ch];
            float w1 = vpW[(4 * i4 + 1) * CHN + ch];
            float w2 = vpW[(4 * i4 + 2) * CHN + ch];
            float w3 = vpW[(4 * i4 + 3) * CHN + ch];
            ull w01 = pk2(w0, w1), w23 = pk2(w2, w3);
            #pragma unroll
            for (int q = 0; q < 4; q++) {
                const ulonglong2 a = *(const ulonglong2*)&g_agg[((size_t)(qg0 + qb + q) * 8 + h) * CHN + 4 * i4];
                a2v[q] = fma2(a.x, w01, a2v[q]);
                a2v[q] = fma2(a.y, w23, a2v[q]);
            }
        }
        float vb = vpb[ch];
        float4 o;
        float lo, hi;
        upk2(a2v[0], lo, hi); o.x = lo + hi + g_bw[(qg0 + qb + 0) * 8 + h] * vb;
        upk2(a2v[1], lo, hi); o.y = lo + hi + g_bw[(qg0 + qb + 1) * 8 + h] * vb;
        upk2(a2v[2], lo, hi); o.z = lo + hi + g_bw[(qg0 + qb + 2) * 8 + h] * vb;
        upk2(a2v[3], lo, hi); o.w = lo + hi + g_bw[(qg0 + qb + 3) * 8 + h] * vb;
        *(float4*)&bufT[ch * TSB + qb] = o;
    }
    __syncthreads();

    // ---- op ----
    ull acc2[2];
    acc2[0] = pk2(g_q[(qg0 + qb + 0) * CHN + ch], g_q[(qg0 + qb + 1) * CHN + ch]);
    acc2[1] = pk2(g_q[(qg0 + qb + 2) * CHN + ch], g_q[(qg0 + qb + 3) * CHN + ch]);
    #pragma unroll 4
    for (int i = 0; i < 256; i++) {
        float w = opW[i * CHN + ch];
        ull w2 = pk2(w, w);
        const ulonglong2 A0 = *(const ulonglong2*)&bufT[i * TSB + qb];
        acc2[0] = fma2(A0.x, w2, acc2[0]);
        acc2[1] = fma2(A0.y, w2, acc2[1]);
    }
    {
        float ob = opb[ch];
        upk2(acc2[0], v[0], v[1]);
        upk2(acc2[1], v[2], v[3]);
        #pragma unroll
        for (int q = 0; q < 4; q++) v[q] += ob;
    }

    // ---- LN1 ----
    ln4h(v, redA, redB, mu, rs, g1, b1, ch, grp, t);
    *(float4*)&qST[ch * TSB + qb] = make_float4(v[0], v[1], v[2], v[3]);
    __syncthreads();

    // ---- FFN ----
    ull o2[2];
    o2[0] = pk2(0.f, 0.f); o2[1] = pk2(0.f, 0.f);
    for (int chunk = 0; chunk < 4; chunk++) {
        ull h2[2];
        h2[0] = pk2(0.f, 0.f); h2[1] = pk2(0.f, 0.f);
        int j = chunk * CHN + ch;
        #pragma unroll 4
        for (int i = 0; i < 256; i++) {
            float w = W1[i * 1024 + j];
            ull w2 = pk2(w, w);
            const ulonglong2 A0 = *(const ulonglong2*)&qST[i * TSB + qb];
            h2[0] = fma2(A0.x, w2, h2[0]);
            h2[1] = fma2(A0.y, w2, h2[1]);
        }
        float bj = fb1[j];
        {
            float a, b_, c, d_;
            upk2(h2[0], a, b_);
            upk2(h2[1], c, d_);
            *(float4*)&bufT[ch * TSB + qb] = make_float4(
                fmaxf(a + bj, 0.f), fmaxf(b_ + bj, 0.f),
                fmaxf(c + bj, 0.f), fmaxf(d_ + bj, 0.f));
        }
        __syncthreads();
        #pragma unroll 4
        for (int i = 0; i < 256; i++) {
            float w = W2[(chunk * CHN + i) * CHN + ch];
            ull w2 = pk2(w, w);
            const ulonglong2 A0 = *(const ulonglong2*)&bufT[i * TSB + qb];
            o2[0] = fma2(A0.x, w2, o2[0]);
            o2[1] = fma2(A0.y, w2, o2[1]);
        }
        __syncthreads();
    }
    {
        float fb = fb2[ch];
        upk2(o2[0], v[0], v[1]);
        upk2(o2[1], v[2], v[3]);
        #pragma unroll
        for (int q = 0; q < 4; q++) v[q] += qST[ch * TSB + qb + q] + fb;
    }

    // ---- LN2 ----
    ln4h(v, redA, redB, mu, rs, g2, b2, ch, grp, t);
    #pragma unroll
    for (int q = 0; q < 4; q++) g_q[(qg0 + qb + q) * CHN + ch] = v[q];

    // ---- fused next-layer so/aw ----
    if (has_next) {
        #pragma unroll
        for (int q = 0; q < 4; q++)
            bufT[ch * TSB + qb + q] = v[q] + g_qpos[(qg0 + qb + q) * CHN + ch];
        __syncthreads();

        if (t < 256) {
            ull s2[4];
            #pragma unroll
            for (int p = 0; p < 4; p++) s2[p] = pk2(0.f, 0.f);
            #pragma unroll 4
            for (int i = 0; i < 256; i++) {
                float w = soWn[i * CHN + t];
                ull w2 = pk2(w, w);
                const ulonglong2 A0 = *(const ulonglong2*)&bufT[i * TSB + 0];
                const ulonglong2 A1 = *(const ulonglong2*)&bufT[i * TSB + 4];
                s2[0] = fma2(A0.x, w2, s2[0]);
                s2[1] = fma2(A0.y, w2, s2[1]);
                s2[2] = fma2(A1.x, w2, s2[2]);
                s2[3] = fma2(A1.y, w2, s2[3]);
            }
            float sbv = sobn[t];
            #pragma unroll
            for (int p = 0; p < 4; p++) {
                float lo, hi;
                upk2(s2[p], lo, hi);
                g_so[(qg0 + 2 * p) * CHN + t]     = lo + sbv;
                g_so[(qg0 + 2 * p + 1) * CHN + t] = hi + sbv;
            }
        } else if (t < 384) {
            int c = t - 256;
            ull s2[4];
            #pragma unroll
            for (int p = 0; p < 4; p++) s2[p] = pk2(0.f, 0.f);
            #pragma unroll 4
            for (int i = 0; i < 256; i++) {
                float w = awWn[i * 128 + c];
                ull w2 = pk2(w, w);
                const ulonglong2 A0 = *(const ulonglong2*)&bufT[i * TSB + 0];
                const ulonglong2 A1 = *(const ulonglong2*)&bufT[i * TSB + 4];
                s2[0] = fma2(A0.x, w2, s2[0]);
                s2[1] = fma2(A0.y, w2, s2[1]);
                s2[2] = fma2(A1.x, w2, s2[2]);
                s2[3] = fma2(A1.y, w2, s2[3]);
            }
            float ab = awbn[c];
            float av[8];
            #pragma unroll
            for (int p = 0; p < 4; p++) {
                upk2(s2[p], av[2 * p], av[2 * p + 1]);
                av[2 * p] += ab; av[2 * p + 1] += ab;
            }
            #pragma unroll
            for (int q = 0; q < 8; q++) {
                float vv = av[q];
                float m = vv;
                #pragma unroll
                for (int o = 8; o > 0; o >>= 1)
                    m = fmaxf(m, __shfl_xor_sync(0xffffffffu, m, o, 16));
                float e = expf(vv - m);
                float s = e;
                #pragma unroll
                for (int o = 8; o > 0; o >>= 1)
                    s += __shfl_xor_sync(0xffffffffu, s, o, 16);
                g_aw[(qg0 + q) * 128 + c] = e / s;
            }
        }
    }
}

// ---------------- K7/K8: zero-fill output, scatter queries ----------------
__global__ void k_zero(float4* __restrict__ out) {
    out[(size_t)blockIdx.x * 256 + threadIdx.x] = make_float4(0.f, 0.f, 0.f, 0.f);
}

__global__ void k_scatter(float* __restrict__ out) {
    int k = blockIdx.x, t = threadIdx.x;
    int b = k >> 10;
    int ind = g_ind[k];
    out[(b * CHN + t) * HWSZ + ind] = g_q[k * CHN + t];
}

// ---------------- launch: two-stream per-half pipeline ----------------
extern "C" void kernel_launch(void* const* d_in, const int* in_sizes, int n_in,
                              void* d_out, int out_size) {
    const float* x    = (const float*)d_in[0];
    const float* preds= (const float*)d_in[1];
    const float* hm   = (const float*)d_in[2];
    const float* mW1  = (const float*)d_in[3];
    const float* mb1  = (const float*)d_in[4];
    const float* mW2  = (const float*)d_in[5];
    const float* mb2  = (const float*)d_in[6];
    const float* tp   = (const float*)d_in[7];
    const float* rowe = (const float*)d_in[8];
    const float* cole = (const float*)d_in[9];
    const float* soW  = (const float*)d_in[10];
    const float* sob  = (const float*)d_in[11];
    const float* awW  = (const float*)d_in[12];
    const float* awb  = (const float*)d_in[13];
    const float* vpW  = (const float*)d_in[14];
    const float* vpb  = (const float*)d_in[15];
    const float* opW  = (const float*)d_in[16];
    const float* opb  = (const float*)d_in[17];
    const float* l1g  = (const float*)d_in[18];
    const float* l1b  = (const float*)d_in[19];
    const float* fW1  = (const float*)d_in[20];
    const float* fb1  = (const float*)d_in[21];
    const float* fW2  = (const float*)d_in[22];
    const float* fb2  = (const float*)d_in[23];
    const float* l2g  = (const float*)d_in[24];
    const float* l2b  = (const float*)d_in[25];
    float* out = (float*)d_out;

    static cudaStream_t sB = nullptr;
    static cudaEvent_t evF = nullptr, evB = nullptr;
    if (sB == nullptr) {
        cudaStreamCreateWithFlags(&sB, cudaStreamNonBlocking);
        cudaEventCreateWithFlags(&evF, cudaEventDisableTiming);
        cudaEventCreateWithFlags(&evB, cudaEventDisableTiming);
    }

    // prologue (main stream)
    k_transpose<<<dim3(4, 8, 1024), 256>>>(x, tp);
    k_score<<<32, 1024>>>(hm);
    k_topk<<<2, 1024>>>();
    k_qinit<<<1024, 256>>>(preds, mW1, mb1, mW2, mb2, rowe, cole);

    // fork: half 0 on main stream, half 1 on sB
    cudaEventRecord(evF, 0);
    cudaStreamWaitEvent(sB, evF, 0);

    k_soaw<<<128, 384>>>(0, soW, sob, awW, awb);
    k_soaw<<<128, 384, 0, sB>>>(KQ, soW, sob, awW, awb);

    for (int l = 0; l < 3; l++) {
        int nl = (l < 2) ? l + 1 : l;
        int hn = (l < 2) ? 1 : 0;
        k_gather<<<1024, 256>>>(0);
        k_tail<<<128, 512>>>(0,
            vpW + l * 65536, vpb + l * 256,
            opW + l * 65536, opb + l * 256,
            l1g + l * 256, l1b + l * 256,
            fW1 + l * 262144, fb1 + l * 1024,
            fW2 + l * 262144, fb2 + l * 256,
            l2g + l * 256, l2b + l * 256,
            soW + nl * 65536, sob + nl * 256,
            awW + nl * 32768, awb + nl * 128, hn);
        k_gather<<<1024, 256, 0, sB>>>(KQ);
        k_tail<<<128, 512, 0, sB>>>(KQ,
            vpW + l * 65536, vpb + l * 256,
            opW + l * 65536, opb + l * 256,
            l1g + l * 256, l1b + l * 256,
            fW1 + l * 262144, fb1 + l * 1024,
            fW2 + l * 262144, fb2 + l * 256,
            l2g + l * 256, l2b + l * 256,
            soW + nl * 65536, sob + nl * 256,
            awW + nl * 32768, awb + nl * 128, hn);
    }

    // half 1 finishes with the output zero-fill (overlaps half 0's tail)
    k_zero<<<8192, 256, 0, sB>>>((float4*)out);
    cudaEventRecord(evB, sB);
    cudaStreamWaitEvent(0, evB, 0);

    k_scatter<<<2048, 256>>>(out);
}